// round 1
// baseline (speedup 1.0000x reference)
#include <cuda_runtime.h>
#include <math.h>

#define BATCH 32768
#define NDIM 25
#define STR 27            // row stride (odd -> conflict-free column walks)
#define WARPS 4
#define NSWEEP 8

__device__ double g_sum_fro;
__device__ double g_sum_eig;
__device__ double g_sum_s;
__device__ double g_sum_absO;
__device__ unsigned int g_max_bits;
__device__ unsigned int g_min_bits;

__global__ void cond_init_kernel() {
    g_sum_fro = 0.0;
    g_sum_eig = 0.0;
    g_sum_s = 0.0;
    g_sum_absO = 0.0;
    g_max_bits = 0u;
    g_min_bits = 0x7f7fffffu;   // +FLT_MAX bits
}

__global__ __launch_bounds__(WARPS * 32)
void cond_main_kernel(const float* __restrict__ inp, const float* __restrict__ outp) {
    __shared__ float smem[WARPS][3][NDIM * STR];
    const int w = threadIdx.x >> 5;
    const int lane = threadIdx.x & 31;
    const int b = blockIdx.x * WARPS + w;

    float* A  = smem[w][0];
    float* Bm = smem[w][1];
    float* C  = smem[w][2];

    const float* O = outp + (size_t)b * 625;
    const float* I = inp  + (size_t)b * 625;

    // Load O -> A, I -> Bm; accumulate sum|O|
    float absO = 0.f;
    for (int idx = lane; idx < 625; idx += 32) {
        int i = idx / 25, j = idx - i * 25;
        float o = O[idx];
        absO += fabsf(o);
        A[i * STR + j]  = o;
        Bm[i * STR + j] = I[idx];
    }
    __syncwarp();

    // C = O @ I  (= ip); accumulate ||ip - I||_F^2
    float frosq = 0.f;
    for (int idx = lane; idx < 625; idx += 32) {
        int i = idx / 25, j = idx - i * 25;
        float acc = 0.f;
        #pragma unroll
        for (int k = 0; k < 25; k++) acc += A[i * STR + k] * Bm[k * STR + j];
        C[i * STR + j] = acc;
        float d = acc - ((i == j) ? 1.f : 0.f);
        frosq += d * d;
    }
    __syncwarp();

    // A = C^T C  (symmetric PSD; eig(A) = S^2)
    for (int idx = lane; idx < 625; idx += 32) {
        int i = idx / 25, j = idx - i * 25;
        float acc = 0.f;
        #pragma unroll
        for (int k = 0; k < 25; k++) acc += C[k * STR + i] * C[k * STR + j];
        A[i * STR + j] = acc;
    }
    __syncwarp();

    // Parallel-order cyclic Jacobi. Round r pairs: {(r+k)%25, (r-k)%25}, k=1..12.
    // 25 rounds cover all C(25,2)=300 pairs exactly once per sweep.
    for (int sweep = 0; sweep < NSWEEP; sweep++) {
        for (int r = 0; r < 25; r++) {
            float c = 1.f, s = 0.f;
            if (lane < 12) {
                int k = lane + 1;
                int p = r + k;        if (p >= 25) p -= 25;
                int q = r + 25 - k;   if (q >= 25) q -= 25;
                float app = A[p * STR + p];
                float aqq = A[q * STR + q];
                float apq = A[p * STR + q];
                if (fabsf(apq) > 1e-20f) {
                    float theta = (aqq - app) / (2.f * apq);
                    float t = 1.f / (fabsf(theta) + sqrtf(1.f + theta * theta));
                    if (theta < 0.f) t = -t;
                    c = rsqrtf(1.f + t * t);
                    s = t * c;
                }
            }
            __syncwarp();

            // Row phase: rows p,q of each pair mixed across all 25 columns.
            #pragma unroll
            for (int tt = 0; tt < 10; tt++) {
                int idx = lane + tt * 32;
                int pr = idx / 25;
                int j = idx - pr * 25;
                bool active = (idx < 300);
                int prc = active ? pr : 0;
                float cc = __shfl_sync(0xffffffffu, c, prc);
                float ss = __shfl_sync(0xffffffffu, s, prc);
                if (active) {
                    int k = prc + 1;
                    int p = r + k;      if (p >= 25) p -= 25;
                    int q = r + 25 - k; if (q >= 25) q -= 25;
                    float mp = A[p * STR + j];
                    float mq = A[q * STR + j];
                    A[p * STR + j] = cc * mp - ss * mq;
                    A[q * STR + j] = ss * mp + cc * mq;
                }
            }
            __syncwarp();

            // Column phase.
            #pragma unroll
            for (int tt = 0; tt < 10; tt++) {
                int idx = lane + tt * 32;
                int pr = idx / 25;
                int i2 = idx - pr * 25;
                bool active = (idx < 300);
                int prc = active ? pr : 0;
                float cc = __shfl_sync(0xffffffffu, c, prc);
                float ss = __shfl_sync(0xffffffffu, s, prc);
                if (active) {
                    int k = prc + 1;
                    int p = r + k;      if (p >= 25) p -= 25;
                    int q = r + 25 - k; if (q >= 25) q -= 25;
                    float mp = A[i2 * STR + p];
                    float mq = A[i2 * STR + q];
                    A[i2 * STR + p] = cc * mp - ss * mq;
                    A[i2 * STR + q] = ss * mp + cc * mq;
                }
            }
            __syncwarp();
        }
    }

    // Gather eigenvalues from diagonal; per-warp partials.
    float sum_e = 0.f, sum_sq = 0.f, maxe = 0.f, mine = 3.0e38f;
    if (lane < 25) {
        float e = A[lane * STR + lane];
        e = fmaxf(e, 1e-12f);
        sum_e = e;
        sum_sq = sqrtf(e);
        maxe = e;
        mine = e;
    }
    #pragma unroll
    for (int off = 16; off > 0; off >>= 1) {
        sum_e  += __shfl_down_sync(0xffffffffu, sum_e, off);
        sum_sq += __shfl_down_sync(0xffffffffu, sum_sq, off);
        frosq  += __shfl_down_sync(0xffffffffu, frosq, off);
        absO   += __shfl_down_sync(0xffffffffu, absO, off);
        maxe = fmaxf(maxe, __shfl_down_sync(0xffffffffu, maxe, off));
        mine = fminf(mine, __shfl_down_sync(0xffffffffu, mine, off));
    }
    if (lane == 0) {
        atomicAdd(&g_sum_fro, (double)sqrtf(frosq));
        atomicAdd(&g_sum_eig, (double)sum_e);
        atomicAdd(&g_sum_s, (double)sum_sq);
        atomicAdd(&g_sum_absO, (double)absO);
        atomicMax(&g_max_bits, __float_as_uint(maxe));
        atomicMin(&g_min_bits, __float_as_uint(mine));
    }
}

__global__ void cond_final_kernel(float* __restrict__ out) {
    double maxe = (double)__uint_as_float(g_max_bits);
    double mine = (double)__uint_as_float(g_min_bits);
    const double NB = (double)BATCH * (double)NDIM;
    double loss = (g_sum_fro / (double)BATCH) * 1e-5                       // INV * mean fro
                + (g_sum_eig / NB - 2.0 * (g_sum_s / NB) + 1.0)            // DEV * mean (S-1)^2
                + 0.5 * (log(maxe) - log(mine)) * 0.01                     // COND * (log max S - log min S)
                + 1e-6 * g_sum_absO;                                        // L1 * sum|outp|
    out[0] = (float)loss;
}

extern "C" void kernel_launch(void* const* d_in, const int* in_sizes, int n_in,
                              void* d_out, int out_size) {
    const float* inp  = (const float*)d_in[0];
    const float* outp = (const float*)d_in[1];
    float* out = (float*)d_out;
    (void)in_sizes; (void)n_in; (void)out_size;

    cond_init_kernel<<<1, 1>>>();
    cond_main_kernel<<<BATCH / WARPS, WARPS * 32>>>(inp, outp);
    cond_final_kernel<<<1, 1>>>(out);
}

// round 2
// speedup vs baseline: 4.6174x; 4.6174x over previous
#include <cuda_runtime.h>
#include <math.h>

#define BATCH  32768
#define NWARPS 8
#define THREADS (NWARPS * 32)
#define NSWEEP 6

__device__ double g_sum_fro;
__device__ double g_sum_eig;
__device__ double g_sum_s;
__device__ double g_sum_absO;
__device__ unsigned int g_max_bits;
__device__ unsigned int g_min_bits;

__global__ void cond_init_kernel() {
    g_sum_fro = 0.0;
    g_sum_eig = 0.0;
    g_sum_s = 0.0;
    g_sum_absO = 0.0;
    g_max_bits = 0u;
    g_min_bits = 0x7f7fffffu;   // +FLT_MAX
}

__global__ __launch_bounds__(THREADS)
void cond_main_kernel(const float* __restrict__ inp, const float* __restrict__ outp) {
    __shared__ float  Osh[NWARPS][625];
    __shared__ double redd[NWARPS][4];
    __shared__ float  redmx[NWARPS];
    __shared__ float  redmn[NWARPS];

    const int w    = threadIdx.x >> 5;
    const int lane = threadIdx.x & 31;
    const int b    = blockIdx.x * NWARPS + w;

    const float* O = outp + (size_t)b * 625;
    const float* I = inp  + (size_t)b * 625;
    float* Os = Osh[w];

    const bool act25 = (lane < 25);

    // Load O into smem (coalesced), accumulate sum|O|
    float absO = 0.f;
    for (int idx = lane; idx < 625; idx += 32) {
        float v = O[idx];
        absO += fabsf(v);
        Os[idx] = v;
    }
    // Load I column `lane` into registers (coalesced across warp per row)
    float Icol[25];
    #pragma unroll
    for (int k = 0; k < 25; k++)
        Icol[k] = act25 ? I[k * 25 + lane] : 0.f;
    __syncwarp();

    // col = column `lane` of C = O @ I ; frosq = sum over column of (C - I)^2
    float col[25];
    float frosq = 0.f;
    #pragma unroll
    for (int i = 0; i < 25; i++) {
        float acc = 0.f;
        #pragma unroll
        for (int k = 0; k < 25; k++)
            acc = fmaf(Os[i * 25 + k], Icol[k], acc);
        col[i] = acc;
        float d = acc - ((i == lane) ? 1.f : 0.f);
        if (act25) frosq += d * d;
    }

    // One-sided (Hestenes) Jacobi on columns of C, register-resident.
    // Round r: lane x pairs with (2r - x) mod 25; covers all 300 pairs / sweep.
    for (int sweep = 0; sweep < NSWEEP; sweep++) {
        for (int r = 0; r < 25; r++) {
            int partner = 2 * r - lane;
            partner %= 25;
            if (partner < 0) partner += 25;
            const bool active = act25 && (partner != lane);

            float o[25];
            float alpha = 0.f, gam = 0.f;
            #pragma unroll
            for (int i = 0; i < 25; i++) {
                o[i] = __shfl_sync(0xffffffffu, col[i], partner);
                alpha = fmaf(col[i], col[i], alpha);
                gam   = fmaf(col[i], o[i], gam);
            }
            float alpha_o = __shfl_sync(0xffffffffu, alpha, partner);

            float c = 1.f, s = 0.f;
            if (active && fabsf(gam) > 1e-28f) {
                float zeta = (alpha_o - alpha) / (2.f * gam);
                float t = 1.f / (fabsf(zeta) + sqrtf(fmaf(zeta, zeta, 1.f)));
                t = copysignf(t, zeta);
                c = rsqrtf(fmaf(t, t, 1.f));
                s = t * c;
            }
            // Both roles reduce to: new = c*self - s_own*other  (s flips sign
            // exactly between the two lanes of a pair).
            #pragma unroll
            for (int i = 0; i < 25; i++)
                col[i] = fmaf(c, col[i], -s * o[i]);
        }
    }

    // Singular values: S_j = ||col_j||
    float alpha = 0.f;
    #pragma unroll
    for (int i = 0; i < 25; i++)
        alpha = fmaf(col[i], col[i], alpha);
    float ac   = fmaxf(alpha, 1e-12f);
    float Sv   = sqrtf(alpha);
    float suma = act25 ? alpha : 0.f;
    float sums = act25 ? Sv : 0.f;
    float mxa  = act25 ? ac : 0.f;
    float mna  = act25 ? ac : 3.0e38f;

    // Warp reduction (butterfly)
    #pragma unroll
    for (int off = 16; off > 0; off >>= 1) {
        suma  += __shfl_xor_sync(0xffffffffu, suma, off);
        sums  += __shfl_xor_sync(0xffffffffu, sums, off);
        frosq += __shfl_xor_sync(0xffffffffu, frosq, off);
        absO  += __shfl_xor_sync(0xffffffffu, absO, off);
        mxa = fmaxf(mxa, __shfl_xor_sync(0xffffffffu, mxa, off));
        mna = fminf(mna, __shfl_xor_sync(0xffffffffu, mna, off));
    }
    if (lane == 0) {
        redd[w][0] = (double)suma;
        redd[w][1] = (double)sums;
        redd[w][2] = (double)sqrtf(frosq);
        redd[w][3] = (double)absO;
        redmx[w] = mxa;
        redmn[w] = mna;
    }
    __syncthreads();

    // Block reduction + one atomic set per block
    if (threadIdx.x == 0) {
        double a0 = 0.0, a1 = 0.0, a2 = 0.0, a3 = 0.0;
        float mx = 0.f, mn = 3.0e38f;
        #pragma unroll
        for (int i = 0; i < NWARPS; i++) {
            a0 += redd[i][0]; a1 += redd[i][1]; a2 += redd[i][2]; a3 += redd[i][3];
            mx = fmaxf(mx, redmx[i]);
            mn = fminf(mn, redmn[i]);
        }
        atomicAdd(&g_sum_eig, a0);
        atomicAdd(&g_sum_s, a1);
        atomicAdd(&g_sum_fro, a2);
        atomicAdd(&g_sum_absO, a3);
        atomicMax(&g_max_bits, __float_as_uint(mx));
        atomicMin(&g_min_bits, __float_as_uint(mn));
    }
}

__global__ void cond_final_kernel(float* __restrict__ out) {
    double maxe = (double)__uint_as_float(g_max_bits);   // max S^2
    double mine = (double)__uint_as_float(g_min_bits);   // min S^2
    const double NB = (double)BATCH * 25.0;
    double loss = (g_sum_fro / (double)BATCH) * 1e-5                 // INV * mean fro
                + (g_sum_eig / NB - 2.0 * (g_sum_s / NB) + 1.0)      // DEV * mean (S-1)^2
                + 0.5 * (log(maxe) - log(mine)) * 0.01               // COND * (log max S - log min S)
                + 1e-6 * g_sum_absO;                                  // L1 * sum|outp|
    out[0] = (float)loss;
}

extern "C" void kernel_launch(void* const* d_in, const int* in_sizes, int n_in,
                              void* d_out, int out_size) {
    const float* inp  = (const float*)d_in[0];
    const float* outp = (const float*)d_in[1];
    float* out = (float*)d_out;
    (void)in_sizes; (void)n_in; (void)out_size;

    cond_init_kernel<<<1, 1>>>();
    cond_main_kernel<<<BATCH / NWARPS, THREADS>>>(inp, outp);
    cond_final_kernel<<<1, 1>>>(out);
}